// round 7
// baseline (speedup 1.0000x reference)
#include <cuda_runtime.h>
#include <cuda_bf16.h>

// Elementwise: y = (x + 1) * 2 / 3; if (y > 0) y -= 5;
// 8192*8192 fp32 = 67,108,864 elements (2^24 float4s). HBM-streaming.
//
// R6: flat8 geometry (8192 blocks x 256 threads, 8 float4/thread,
// front-batched __ldcg loads) + __stwt write-through stores (probe:
// avoid L2 write-allocate contention with read fills at the LTS).
// Wallclock is pinned at 512MB / sustained-HBM-BW (~82.4us floor).

__device__ __forceinline__ float4 transform4(float4 v) {
    const float c = 2.0f / 3.0f;   // (x+1)*2/3 == fma(x, 2/3, 2/3)
    float4 r;
    r.x = fmaf(v.x, c, c);
    r.y = fmaf(v.y, c, c);
    r.z = fmaf(v.z, c, c);
    r.w = fmaf(v.w, c, c);
    if (r.x > 0.0f) r.x -= 5.0f;
    if (r.y > 0.0f) r.y -= 5.0f;
    if (r.z > 0.0f) r.z -= 5.0f;
    if (r.w > 0.0f) r.w -= 5.0f;
    return r;
}

// Each block handles 256 threads * 8 float4 = 2048 float4s. No bounds checks;
// launcher guarantees exact divisibility on the fast path.
__global__ __launch_bounds__(256) void ew_flat8_wt(const float4* __restrict__ x,
                                                   float4* __restrict__ out) {
    int base = blockIdx.x * (256 * 8) + threadIdx.x;

    float4 v0 = __ldcg(x + base + 0 * 256);
    float4 v1 = __ldcg(x + base + 1 * 256);
    float4 v2 = __ldcg(x + base + 2 * 256);
    float4 v3 = __ldcg(x + base + 3 * 256);
    __stwt(out + base + 0 * 256, transform4(v0));
    __stwt(out + base + 1 * 256, transform4(v1));
    __stwt(out + base + 2 * 256, transform4(v2));
    __stwt(out + base + 3 * 256, transform4(v3));

    float4 v4 = __ldcg(x + base + 4 * 256);
    float4 v5 = __ldcg(x + base + 5 * 256);
    float4 v6 = __ldcg(x + base + 6 * 256);
    float4 v7 = __ldcg(x + base + 7 * 256);
    __stwt(out + base + 4 * 256, transform4(v4));
    __stwt(out + base + 5 * 256, transform4(v5));
    __stwt(out + base + 6 * 256, transform4(v6));
    __stwt(out + base + 7 * 256, transform4(v7));
}

// Fallback grid-stride for arbitrary sizes.
__global__ __launch_bounds__(256) void ew_gs(const float4* __restrict__ x,
                                             float4* __restrict__ out, int n4) {
    int i = blockIdx.x * blockDim.x + threadIdx.x;
    int stride = gridDim.x * blockDim.x;
    for (; i < n4; i += stride)
        out[i] = transform4(__ldcg(x + i));
}

__global__ void ew_scalar_tail(const float* __restrict__ x,
                               float* __restrict__ out, int start, int n) {
    int i = start + blockIdx.x * blockDim.x + threadIdx.x;
    if (i < n) {
        const float c = 2.0f / 3.0f;
        float r = fmaf(x[i], c, c);
        if (r > 0.0f) r -= 5.0f;
        out[i] = r;
    }
}

extern "C" void kernel_launch(void* const* d_in, const int* in_sizes, int n_in,
                              void* d_out, int out_size) {
    const float* x = (const float*)d_in[0];
    float* out = (float*)d_out;
    int n = in_sizes[0];          // 67,108,864
    int n4 = n >> 2;              // 16,777,216 = 2^24

    const int per_block = 256 * 8;  // 2048 float4s per block
    if ((n % 4) == 0 && (n4 % per_block) == 0) {
        int blocks = n4 / per_block;  // 8192
        ew_flat8_wt<<<blocks, 256>>>((const float4*)x, (float4*)out);
    } else {
        int n4f = n >> 2;
        if (n4f > 0) {
            int b = (n4f + 256 * 8 - 1) / (256 * 8);
            ew_gs<<<b, 256>>>((const float4*)x, (float4*)out, n4f);
        }
        int tail = n - (n4f << 2);
        if (tail > 0)
            ew_scalar_tail<<<(tail + 255) / 256, 256>>>(x, out, n4f << 2, n);
    }
}

// round 8
// speedup vs baseline: 1.0136x; 1.0136x over previous
#include <cuda_runtime.h>
#include <cuda_bf16.h>

// Elementwise: y = (x + 1) * 2 / 3; if (y > 0) y -= 5;
// 8192*8192 fp32 = 67,108,864 elements (2^24 float4s). HBM-streaming.
//
// FINAL (= R5, best measured: 82.43us). Flat loop-free kernel:
// 8192 blocks x 256 threads, 8 float4/thread in two front-batched groups
// of 4 independent __ldcg (L2-only) loads; default (write-back) stores.
//
// Session evidence: wallclock is pinned at total-traffic/sustained-HBM-BW
// (512 MB / ~6.2 TB/s ~= 82.4us). All SM-side variants (MLP depth, loop vs
// flat, grid size, .cs/.wt cache hints) land in 82.4-83.6us; __stwt and
// .cs both measured worse; __ldcg measured best. This is the roofline.

__device__ __forceinline__ float4 transform4(float4 v) {
    const float c = 2.0f / 3.0f;   // (x+1)*2/3 == fma(x, 2/3, 2/3)
    float4 r;
    r.x = fmaf(v.x, c, c);
    r.y = fmaf(v.y, c, c);
    r.z = fmaf(v.z, c, c);
    r.w = fmaf(v.w, c, c);
    if (r.x > 0.0f) r.x -= 5.0f;
    if (r.y > 0.0f) r.y -= 5.0f;
    if (r.z > 0.0f) r.z -= 5.0f;
    if (r.w > 0.0f) r.w -= 5.0f;
    return r;
}

// Each block handles 256 threads * 8 float4 = 2048 float4s. No bounds checks;
// launcher guarantees exact divisibility on the fast path.
__global__ __launch_bounds__(256) void ew_flat8(const float4* __restrict__ x,
                                                float4* __restrict__ out) {
    int base = blockIdx.x * (256 * 8) + threadIdx.x;

    float4 v0 = __ldcg(x + base + 0 * 256);
    float4 v1 = __ldcg(x + base + 1 * 256);
    float4 v2 = __ldcg(x + base + 2 * 256);
    float4 v3 = __ldcg(x + base + 3 * 256);
    out[base + 0 * 256] = transform4(v0);
    out[base + 1 * 256] = transform4(v1);
    out[base + 2 * 256] = transform4(v2);
    out[base + 3 * 256] = transform4(v3);

    float4 v4 = __ldcg(x + base + 4 * 256);
    float4 v5 = __ldcg(x + base + 5 * 256);
    float4 v6 = __ldcg(x + base + 6 * 256);
    float4 v7 = __ldcg(x + base + 7 * 256);
    out[base + 4 * 256] = transform4(v4);
    out[base + 5 * 256] = transform4(v5);
    out[base + 6 * 256] = transform4(v6);
    out[base + 7 * 256] = transform4(v7);
}

// Fallback grid-stride for arbitrary sizes.
__global__ __launch_bounds__(256) void ew_gs(const float4* __restrict__ x,
                                             float4* __restrict__ out, int n4) {
    int i = blockIdx.x * blockDim.x + threadIdx.x;
    int stride = gridDim.x * blockDim.x;
    for (; i < n4; i += stride)
        out[i] = transform4(__ldcg(x + i));
}

__global__ void ew_scalar_tail(const float* __restrict__ x,
                               float* __restrict__ out, int start, int n) {
    int i = start + blockIdx.x * blockDim.x + threadIdx.x;
    if (i < n) {
        const float c = 2.0f / 3.0f;
        float r = fmaf(x[i], c, c);
        if (r > 0.0f) r -= 5.0f;
        out[i] = r;
    }
}

extern "C" void kernel_launch(void* const* d_in, const int* in_sizes, int n_in,
                              void* d_out, int out_size) {
    const float* x = (const float*)d_in[0];
    float* out = (float*)d_out;
    int n = in_sizes[0];          // 67,108,864
    int n4 = n >> 2;              // 16,777,216 = 2^24

    const int per_block = 256 * 8;  // 2048 float4s per block
    if ((n % 4) == 0 && (n4 % per_block) == 0) {
        int blocks = n4 / per_block;  // 8192
        ew_flat8<<<blocks, 256>>>((const float4*)x, (float4*)out);
    } else {
        int n4f = n >> 2;
        if (n4f > 0) {
            int b = (n4f + 256 * 8 - 1) / (256 * 8);
            ew_gs<<<b, 256>>>((const float4*)x, (float4*)out, n4f);
        }
        int tail = n - (n4f << 2);
        if (tail > 0)
            ew_scalar_tail<<<(tail + 255) / 256, 256>>>(x, out, n4f << 2, n);
    }
}

// round 9
// speedup vs baseline: 1.0160x; 1.0023x over previous
#include <cuda_runtime.h>
#include <cuda_bf16.h>

// Elementwise: y = (x + 1) * 2 / 3; if (y > 0) y -= 5;
// 8192*8192 fp32 = 67,108,864 elements (2^24 float4s). HBM-streaming.
//
// R8 probe: same flat8 + __ldcg recipe as the proven-best kernel (82.43us),
// but 512-thread blocks (4096 blocks total) -- halves CTA scheduling events
// per replay. Wallclock floor = 512 MB / ~6.2 TB/s sustained HBM.

__device__ __forceinline__ float4 transform4(float4 v) {
    const float c = 2.0f / 3.0f;   // (x+1)*2/3 == fma(x, 2/3, 2/3)
    float4 r;
    r.x = fmaf(v.x, c, c);
    r.y = fmaf(v.y, c, c);
    r.z = fmaf(v.z, c, c);
    r.w = fmaf(v.w, c, c);
    if (r.x > 0.0f) r.x -= 5.0f;
    if (r.y > 0.0f) r.y -= 5.0f;
    if (r.z > 0.0f) r.z -= 5.0f;
    if (r.w > 0.0f) r.w -= 5.0f;
    return r;
}

// Each block: 512 threads * 8 float4 = 4096 float4s. No bounds checks;
// launcher guarantees exact divisibility on the fast path.
__global__ __launch_bounds__(512) void ew_flat8_b512(const float4* __restrict__ x,
                                                     float4* __restrict__ out) {
    int base = blockIdx.x * (512 * 8) + threadIdx.x;

    float4 v0 = __ldcg(x + base + 0 * 512);
    float4 v1 = __ldcg(x + base + 1 * 512);
    float4 v2 = __ldcg(x + base + 2 * 512);
    float4 v3 = __ldcg(x + base + 3 * 512);
    out[base + 0 * 512] = transform4(v0);
    out[base + 1 * 512] = transform4(v1);
    out[base + 2 * 512] = transform4(v2);
    out[base + 3 * 512] = transform4(v3);

    float4 v4 = __ldcg(x + base + 4 * 512);
    float4 v5 = __ldcg(x + base + 5 * 512);
    float4 v6 = __ldcg(x + base + 6 * 512);
    float4 v7 = __ldcg(x + base + 7 * 512);
    out[base + 4 * 512] = transform4(v4);
    out[base + 5 * 512] = transform4(v5);
    out[base + 6 * 512] = transform4(v6);
    out[base + 7 * 512] = transform4(v7);
}

// Fallback grid-stride for arbitrary sizes.
__global__ __launch_bounds__(256) void ew_gs(const float4* __restrict__ x,
                                             float4* __restrict__ out, int n4) {
    int i = blockIdx.x * blockDim.x + threadIdx.x;
    int stride = gridDim.x * blockDim.x;
    for (; i < n4; i += stride)
        out[i] = transform4(__ldcg(x + i));
}

__global__ void ew_scalar_tail(const float* __restrict__ x,
                               float* __restrict__ out, int start, int n) {
    int i = start + blockIdx.x * blockDim.x + threadIdx.x;
    if (i < n) {
        const float c = 2.0f / 3.0f;
        float r = fmaf(x[i], c, c);
        if (r > 0.0f) r -= 5.0f;
        out[i] = r;
    }
}

extern "C" void kernel_launch(void* const* d_in, const int* in_sizes, int n_in,
                              void* d_out, int out_size) {
    const float* x = (const float*)d_in[0];
    float* out = (float*)d_out;
    int n = in_sizes[0];          // 67,108,864
    int n4 = n >> 2;              // 16,777,216 = 2^24

    const int per_block = 512 * 8;  // 4096 float4s per block
    if ((n % 4) == 0 && (n4 % per_block) == 0) {
        int blocks = n4 / per_block;  // 4096
        ew_flat8_b512<<<blocks, 512>>>((const float4*)x, (float4*)out);
    } else {
        int n4f = n >> 2;
        if (n4f > 0) {
            int b = (n4f + 256 * 8 - 1) / (256 * 8);
            ew_gs<<<b, 256>>>((const float4*)x, (float4*)out, n4f);
        }
        int tail = n - (n4f << 2);
        if (tail > 0)
            ew_scalar_tail<<<(tail + 255) / 256, 256>>>(x, out, n4f << 2, n);
    }
}